// round 2
// baseline (speedup 1.0000x reference)
#include <cuda_runtime.h>
#include <math.h>

#define TT 4
#define BB 16
#define CC 512
#define NN 1024
#define NHEADS 8

// ---------------- device scratch (no allocations allowed) ----------------
__device__ float g_Wqk[CC * 1024];        // [c][0..511 = q_d, 512..1023 = k_d], BN-folded
__device__ float g_Wp[CC * CC];           // [c][d], BN-folded proj
__device__ float g_bqk[1024];
__device__ float g_bp[CC];
__device__ unsigned g_xs_cmask[TT * BB * NN * 16];  // spike mask over channels, [t][b][n][c/32]
__device__ unsigned g_y_cmask[TT * BB * NN * 16];
__device__ float g_attn_fallback[TT * BB * NHEADS * NN];

// ---------------- K0: fold BN into weights ----------------
__global__ void prep_kernel(const float* __restrict__ qw, const float* __restrict__ qg,
                            const float* __restrict__ qb, const float* __restrict__ qm,
                            const float* __restrict__ qv,
                            const float* __restrict__ kw, const float* __restrict__ kg,
                            const float* __restrict__ kb, const float* __restrict__ km,
                            const float* __restrict__ kv,
                            const float* __restrict__ pw, const float* __restrict__ pbias,
                            const float* __restrict__ pg, const float* __restrict__ pb,
                            const float* __restrict__ pm, const float* __restrict__ pv) {
    int idx = blockIdx.x * blockDim.x + threadIdx.x;  // 512*512
    int d = idx & 511;
    int c = idx >> 9;
    float invq = (float)((double)qg[d] / sqrt((double)qv[d] + 1e-5));
    float invk = (float)((double)kg[d] / sqrt((double)kv[d] + 1e-5));
    float invp = (float)((double)pg[d] / sqrt((double)pv[d] + 1e-5));
    g_Wqk[c * 1024 + d]       = qw[d * CC + c] * invq;
    g_Wqk[c * 1024 + 512 + d] = kw[d * CC + c] * invk;
    g_Wp[c * CC + d]          = pw[d * CC + c] * invp;
    if (c == 0) {
        g_bqk[d]       = qb[d] - qm[d] * invq;
        g_bqk[512 + d] = kb[d] - km[d] * invk;
        g_bp[d]        = pbias[d] * invp + pb[d] - pm[d] * invp;
    }
}

// ---------------- K1: LIF over x, pack channel bitmasks ----------------
// block: 1024 threads = 32 c x 32 n tile; grid: b(16) x cblk(16) x nblk(32)
__global__ __launch_bounds__(1024) void lif_x_kernel(const float* __restrict__ x) {
    int tid = threadIdx.x;
    int bid = blockIdx.x;
    int nblk = bid & 31;
    int cblk = (bid >> 5) & 15;
    int b = bid >> 9;
    int c_l = tid >> 5, n_l = tid & 31;
    int c = cblk * 32 + c_l;
    int n = nblk * 32 + n_l;
    __shared__ unsigned sw[32];
    float v = 0.f;
    const float* xp = x + ((size_t)b * CC + c) * NN + n;
#pragma unroll
    for (int t = 0; t < TT; t++) {
        float xv = xp[(size_t)t * BB * CC * NN];
        v = v + (xv - v) * 0.5f;
        bool s = (v >= 1.0f);
        if (s) v = 0.f;
        unsigned bm = __ballot_sync(0xffffffffu, s);  // lanes = n within this c
        if (n_l == 0) sw[c_l] = bm;
        __syncthreads();
        // transpose 32x32 bits -> word over c for each n
        int n2 = tid >> 5, c2 = tid & 31;
        bool bit = (sw[c2] >> n2) & 1u;
        unsigned cword = __ballot_sync(0xffffffffu, bit);  // lanes = c
        if (c2 == 0) {
            g_xs_cmask[(((size_t)(t * BB + b)) * NN + nblk * 32 + n2) * 16 + cblk] = cword;
        }
        __syncthreads();
    }
}

// deterministic active-list build from 16 mask words (warp 0 only)
__device__ __forceinline__ void build_list(const unsigned* mwords, unsigned short* list,
                                           int* nact_s, int lane) {
    unsigned m = (lane < 16) ? mwords[lane] : 0u;
    int cnt = __popc(m);
    int incl = cnt;
#pragma unroll
    for (int d = 1; d < 32; d <<= 1) {
        int v2 = __shfl_up_sync(0xffffffffu, incl, d);
        if (lane >= d) incl += v2;
    }
    int off = incl - cnt;
    int total = __shfl_sync(0xffffffffu, incl, 31);
    if (lane == 0) *nact_s = total;
    int base = lane * 32;
    while (m) {
        int cb = __ffs(m) - 1;
        list[off++] = (unsigned short)(base + cb);
        m &= m - 1;
    }
}

// ---------------- K2: fused sparse q/k GEMM + LIF + qh + attn LIF + y mask ----------------
// one block per (b, n) column; 512 threads, thread tid = channel d for both q and k
__global__ __launch_bounds__(512) void fused_qk_kernel(float* __restrict__ out_attn) {
    int tid = threadIdx.x;
    int lane = tid & 31, warp = tid >> 5;
    int bid = blockIdx.x;
    int n = bid & (NN - 1);
    int b = bid >> 10;

    __shared__ unsigned short list[512];
    __shared__ int nact_s;
    __shared__ unsigned mwords[16];
    __shared__ int qcnt[16];
    __shared__ unsigned attn_bits_s;

    float vq = 0.f, vk = 0.f, va = 0.f;
    const float bq = g_bqk[tid];
    const float bk = g_bqk[512 + tid];

    for (int t = 0; t < TT; t++) {
        size_t colbase = (((size_t)(t * BB + b)) * NN + n) * 16;
        if (tid < 16) mwords[tid] = g_xs_cmask[colbase + tid];
        __syncthreads();
        if (warp == 0) build_list(mwords, list, &nact_s, lane);
        __syncthreads();

        int na = nact_s;
        float aq = bq, ak = bk;
        int i = 0;
        for (; i + 4 <= na; i += 4) {
            int c0 = list[i], c1 = list[i + 1], c2 = list[i + 2], c3 = list[i + 3];
            float q0 = g_Wqk[c0 * 1024 + tid],       k0 = g_Wqk[c0 * 1024 + 512 + tid];
            float q1 = g_Wqk[c1 * 1024 + tid],       k1 = g_Wqk[c1 * 1024 + 512 + tid];
            float q2 = g_Wqk[c2 * 1024 + tid],       k2 = g_Wqk[c2 * 1024 + 512 + tid];
            float q3 = g_Wqk[c3 * 1024 + tid],       k3 = g_Wqk[c3 * 1024 + 512 + tid];
            aq += q0; ak += k0;
            aq += q1; ak += k1;
            aq += q2; ak += k2;
            aq += q3; ak += k3;
        }
        for (; i < na; i++) {
            int c0 = list[i];
            aq += g_Wqk[c0 * 1024 + tid];
            ak += g_Wqk[c0 * 1024 + 512 + tid];
        }

        // LIF(q), LIF(k): v = v + (x - v)/2; spike if v >= 1; hard reset
        vq = vq + (aq - vq) * 0.5f;
        bool sq = (vq >= 1.0f);
        if (sq) vq = 0.f;
        vk = vk + (ak - vk) * 0.5f;
        bool sk = (vk >= 1.0f);
        if (sk) vk = 0.f;

        // qh = sum of q spikes over Dh=64 per head (2 warps per head)
        unsigned qbits = __ballot_sync(0xffffffffu, sq);
        if (lane == 0) qcnt[warp] = __popc(qbits);
        __syncthreads();

        if (warp == 0) {
            bool sa = false;
            if (lane < 8) {
                float qh = (float)(qcnt[2 * lane] + qcnt[2 * lane + 1]);
                va = va + (qh - va) * 0.5f;
                sa = (va >= 0.5f);
                if (sa) va = 0.f;
                out_attn[(((size_t)(t * BB + b)) * NHEADS + lane) * NN + n] = sa ? 1.f : 0.f;
            }
            unsigned ab = __ballot_sync(0xffffffffu, sa);
            if (lane == 0) attn_bits_s = ab;
        }
        __syncthreads();

        bool y = sk && ((attn_bits_s >> (tid >> 6)) & 1u);
        unsigned yw = __ballot_sync(0xffffffffu, y);
        if (lane == 0) g_y_cmask[colbase + warp] = yw;
        __syncthreads();
    }
}

// ---------------- K3: sparse proj GEMM + bias/BN, staged coalesced writes ----------------
// block: (t, b, 16-column group); 512 threads = channel d
__global__ __launch_bounds__(512) void proj_kernel(float* __restrict__ out) {
    int tid = threadIdx.x;
    int lane = tid & 31, warp = tid >> 5;
    int bid = blockIdx.x;  // t*BB*64 + b*64 + ng
    int ng = bid & 63;
    int b = (bid >> 6) & 15;
    int t = bid >> 10;
    int n0 = ng * 16;

    __shared__ float stage[512 * 17];
    __shared__ unsigned short list[512];
    __shared__ int nact_s;
    __shared__ unsigned mwords[16];

    const float bpv = g_bp[tid];

    for (int j = 0; j < 16; j++) {
        int n = n0 + j;
        size_t colbase = (((size_t)(t * BB + b)) * NN + n) * 16;
        if (tid < 16) mwords[tid] = g_y_cmask[colbase + tid];
        __syncthreads();
        if (warp == 0) build_list(mwords, list, &nact_s, lane);
        __syncthreads();
        int na = nact_s;
        float acc = bpv;
        for (int i = 0; i < na; i++) acc += g_Wp[(int)list[i] * CC + tid];
        stage[tid * 17 + j] = acc;
        __syncthreads();
    }

    size_t obase = ((size_t)(t * BB + b)) * CC * NN + n0;
#pragma unroll
    for (int r = 0; r < 16; r++) {
        int idx = r * 512 + tid;
        int d = idx >> 4, j = idx & 15;
        out[obase + (size_t)d * NN + j] = stage[d * 17 + j];
    }
    (void)warp;
}

// ---------------- launch ----------------
extern "C" void kernel_launch(void* const* d_in, const int* in_sizes, int n_in,
                              void* d_out, int out_size) {
    const float* x      = (const float*)d_in[0];
    const float* q_w    = (const float*)d_in[1];
    const float* q_g    = (const float*)d_in[2];
    const float* q_b    = (const float*)d_in[3];
    const float* q_m    = (const float*)d_in[4];
    const float* q_v    = (const float*)d_in[5];
    const float* k_w    = (const float*)d_in[6];
    const float* k_g    = (const float*)d_in[7];
    const float* k_b    = (const float*)d_in[8];
    const float* k_m    = (const float*)d_in[9];
    const float* k_v    = (const float*)d_in[10];
    const float* p_w    = (const float*)d_in[11];
    const float* p_bias = (const float*)d_in[12];
    const float* p_g    = (const float*)d_in[13];
    const float* p_b    = (const float*)d_in[14];
    const float* p_m    = (const float*)d_in[15];
    const float* p_v    = (const float*)d_in[16];

    float* out = (float*)d_out;
    const size_t Y_ELEMS = (size_t)TT * BB * CC * NN;           // 33,554,432
    const size_t A_ELEMS = (size_t)TT * BB * NHEADS * NN;       // 524,288

    float* attn_ptr;
    if ((size_t)out_size >= Y_ELEMS + A_ELEMS) {
        attn_ptr = out + Y_ELEMS;
    } else {
        void* p = nullptr;
        cudaGetSymbolAddress(&p, g_attn_fallback);
        attn_ptr = (float*)p;
    }

    prep_kernel<<<512, 512>>>(q_w, q_g, q_b, q_m, q_v,
                              k_w, k_g, k_b, k_m, k_v,
                              p_w, p_bias, p_g, p_b, p_m, p_v);
    lif_x_kernel<<<16 * 16 * 32, 1024>>>(x);
    fused_qk_kernel<<<BB * NN, 512>>>(attn_ptr);
    proj_kernel<<<TT * BB * 64, 512>>>(out);
}